// round 14
// baseline (speedup 1.0000x reference)
#include <cuda_runtime.h>
#include <cstdint>
#include <math.h>

// Problem shape (fixed by the reference)
#define NB 32
#define NT 2048
#define ND 128
#define CH 8           // timesteps per thread-chunk
#define NC 256         // NT / CH
#define PD 12          // probe depth per direction (single round trip)

// ---------------------------------------------------------------------------
// Single fused kernel. Thread = (b, chunk c, lane pair).
// Probe strategy: one unconditional 12-deep batch per direction resolved via
// __ffs (P(lane fallback) = 2^-12). c is warp-uniform, so the interior/edge
// branch is non-divergent; the interior path (252/256 chunks) uses pure
// base +/- k*128 immediate-offset loads with no clamping or range masks.
// Payload v/t loads stay inline in the sweeps; backward sweep re-loads t.
// ---------------------------------------------------------------------------
__global__ void __launch_bounds__(128, 9)
k_all(const float* __restrict__ v, const float* __restrict__ t,
      const void* __restrict__ mraw, float* __restrict__ out) {
    // ---- mask dtype detection: int32 0/1 words are always <=1; packed bool
    // bytes give a word >1 over 32 words w.p. 1-(1/8)^32. Bool-as-int32 0/1
    // takes the int path, which is also correct.
    __shared__ int s_isb;
    if (threadIdx.x < 32) {
        unsigned int w = ((const unsigned int*)mraw)[threadIdx.x];
        unsigned int any = __ballot_sync(0xffffffffu, w > 1u);
        if (threadIdx.x == 0) s_isb = (any != 0u);
    }
    __syncthreads();
    const bool isb = (s_isb != 0);

    const int gid = blockIdx.x * 128 + threadIdx.x;
    const int dg = gid & 63;                 // ND/2 = 64 lane pairs
    const int c  = (gid >> 6) & (NC - 1);    // warp-uniform
    const int b  = gid >> 14;                // 6 + log2(NC)
    const int d2 = dg * 2;

    const float2* v2 = (const float2*)v;
    const float2* t2 = (const float2*)t;
    float2* o2 = (float2*)out;

    const int rb  = b * NT * ND + d2;            // scalar row base (lane 0)
    const int rb2 = b * NT * (ND / 2) + dg;      // float2/int2 row base
    const int base2 = rb2 + (c * CH) * (ND / 2);
    const unsigned char* m8 = (const unsigned char*)mraw;
    const int2* m32 = (const int2*)mraw;

    const int fstart = c * CH - 1;
    const int bstart = (c + 1) * CH;
    const bool interior = (c >= 2) && (c <= NC - 3);   // warp-uniform branch

    // ---- one latency window: chunk bits + both probe batches ----
    unsigned int bA = 0, bB = 0;     // chunk mask bits
    unsigned int fA = 0, fB = 0;     // forward probe bits (bit k = row fstart-k)
    unsigned int nA = 0, nB = 0;     // backward probe bits (bit k = row bstart+k)

    if (isb) {
        const unsigned char* pc = m8 + rb + (c * CH) * ND;
#pragma unroll
        for (int tt = 0; tt < CH; ++tt) {
            unsigned int w = *(const unsigned short*)(pc + tt * ND);
            unsigned int r = __vcmpne4(w, 0u);    // 0xff per nonzero byte
            bA |= (r & 1u) << tt;
            bB |= ((r >> 8) & 1u) << tt;
        }
        if (interior) {
            const unsigned char* pf = m8 + rb + fstart * ND;
            const unsigned char* pb = m8 + rb + bstart * ND;
#pragma unroll
            for (int k = 0; k < PD; ++k) {        // immediate offsets -k*128
                unsigned int w = *(const unsigned short*)(pf - k * ND);
                unsigned int r = __vcmpne4(w, 0u);
                fA |= (r & 1u) << k;
                fB |= ((r >> 8) & 1u) << k;
            }
#pragma unroll
            for (int k = 0; k < PD; ++k) {        // immediate offsets +k*128
                unsigned int w = *(const unsigned short*)(pb + k * ND);
                unsigned int r = __vcmpne4(w, 0u);
                nA |= (r & 1u) << k;
                nB |= ((r >> 8) & 1u) << k;
            }
        } else {
            const int vf = min(fstart + 1, PD);
            const int vb = min(NT - bstart, PD);
            const unsigned int fmask = (vf > 0) ? ((1u << vf) - 1u) : 0u;
            const unsigned int bmask = (vb > 0) ? ((1u << vb) - 1u) : 0u;
#pragma unroll
            for (int k = 0; k < PD; ++k) {
                int row = max(fstart - k, 0);
                unsigned int w = *(const unsigned short*)(m8 + rb + row * ND);
                unsigned int r = __vcmpne4(w, 0u);
                fA |= (r & 1u) << k;
                fB |= ((r >> 8) & 1u) << k;
            }
#pragma unroll
            for (int k = 0; k < PD; ++k) {
                int row = min(bstart + k, NT - 1);
                unsigned int w = *(const unsigned short*)(m8 + rb + row * ND);
                unsigned int r = __vcmpne4(w, 0u);
                nA |= (r & 1u) << k;
                nB |= ((r >> 8) & 1u) << k;
            }
            fA &= fmask; fB &= fmask;
            nA &= bmask; nB &= bmask;
        }
    } else {
#pragma unroll
        for (int tt = 0; tt < CH; ++tt) {
            int2 w = m32[base2 + tt * (ND / 2)];
            bA |= (w.x ? 1u : 0u) << tt;
            bB |= (w.y ? 1u : 0u) << tt;
        }
        if (interior) {
            const int2* pf = m32 + rb2 + fstart * (ND / 2);
            const int2* pb = m32 + rb2 + bstart * (ND / 2);
#pragma unroll
            for (int k = 0; k < PD; ++k) {
                int2 w = pf[-k * (ND / 2)];
                fA |= (w.x ? 1u : 0u) << k;
                fB |= (w.y ? 1u : 0u) << k;
            }
#pragma unroll
            for (int k = 0; k < PD; ++k) {
                int2 w = pb[k * (ND / 2)];
                nA |= (w.x ? 1u : 0u) << k;
                nB |= (w.y ? 1u : 0u) << k;
            }
        } else {
            const int vf = min(fstart + 1, PD);
            const int vb = min(NT - bstart, PD);
            const unsigned int fmask = (vf > 0) ? ((1u << vf) - 1u) : 0u;
            const unsigned int bmask = (vb > 0) ? ((1u << vb) - 1u) : 0u;
#pragma unroll
            for (int k = 0; k < PD; ++k) {
                int row = max(fstart - k, 0);
                int2 w = m32[rb2 + row * (ND / 2)];
                fA |= (w.x ? 1u : 0u) << k;
                fB |= (w.y ? 1u : 0u) << k;
            }
#pragma unroll
            for (int k = 0; k < PD; ++k) {
                int row = min(bstart + k, NT - 1);
                int2 w = m32[rb2 + row * (ND / 2)];
                nA |= (w.x ? 1u : 0u) << k;
                nB |= (w.y ? 1u : 0u) << k;
            }
            fA &= fmask; fB &= fmask;
            nA &= bmask; nB &= bmask;
        }
    }

    // ---- resolve probe bits -> row indices ----
    int f0 = fA ? fstart - (__ffs(fA) - 1) : -1;
    int f1 = fB ? fstart - (__ffs(fB) - 1) : -1;
    int n0i = nA ? bstart + (__ffs(nA) - 1) : -1;
    int n1i = nB ? bstart + (__ffs(nB) - 1) : -1;

    {   // forward fallback: P ~ 2^-12 per lane
        int ti = fstart - PD;
        while ((f0 < 0 || f1 < 0) && ti >= 0) {
            unsigned int a, bb;
            if (isb) {
                unsigned short w = *(const unsigned short*)(m8 + rb + ti * ND);
                a = w & 0xffu; bb = w >> 8;
            } else {
                int2 w = m32[rb2 + ti * (ND / 2)];
                a = w.x; bb = w.y;
            }
            if (f0 < 0 && a)  f0 = ti;
            if (f1 < 0 && bb) f1 = ti;
            --ti;
        }
    }
    {   // backward fallback
        int ti = bstart + PD;
        while ((n0i < 0 || n1i < 0) && ti < NT) {
            unsigned int a, bb;
            if (isb) {
                unsigned short w = *(const unsigned short*)(m8 + rb + ti * ND);
                a = w & 0xffu; bb = w >> 8;
            } else {
                int2 w = m32[rb2 + ti * (ND / 2)];
                a = w.x; bb = w.y;
            }
            if (n0i < 0 && a)  n0i = ti;
            if (n1i < 0 && bb) n1i = ti;
            ++ti;
        }
    }

    // ---- seed gathers (both directions issued together) ----
    float lx0 = 0.f, lx1 = 0.f, lt0, lt1;
    if (f0 >= 0) { lx0 = v[rb + f0 * ND];     lt0 = t[rb + f0 * ND];     } else lt0 = t[rb];
    if (f1 >= 0) { lx1 = v[rb + 1 + f1 * ND]; lt1 = t[rb + 1 + f1 * ND]; } else lt1 = t[rb + 1];
    float nx0 = 0.f, nx1 = 0.f, nt0, nt1;
    if (n0i >= 0) { nx0 = v[rb + n0i * ND];     nt0 = t[rb + n0i * ND];     } else nt0 = t[rb + (NT - 1) * ND];
    if (n1i >= 0) { nx1 = v[rb + 1 + n1i * ND]; nt1 = t[rb + 1 + n1i * ND]; } else nt1 = t[rb + 1 + (NT - 1) * ND];

    // ---- forward sweep: inclusive forward fill into registers ----
    float2 LX[CH], LT[CH];
#pragma unroll
    for (int tt = 0; tt < CH; ++tt) {
        float2 vv = v2[base2 + tt * (ND / 2)];
        float2 tv = t2[base2 + tt * (ND / 2)];
        if ((bA >> tt) & 1u) { lx0 = vv.x; lt0 = tv.x; }
        if ((bB >> tt) & 1u) { lx1 = vv.y; lt1 = tv.y; }
        LX[tt] = make_float2(lx0, lx1);
        LT[tt] = make_float2(lt0, lt1);
    }

    // ---- backward sweep: re-load t (L1 hits), backward fill + interpolate ----
#pragma unroll
    for (int tt = CH - 1; tt >= 0; --tt) {
        float2 tv2 = t2[base2 + tt * (ND / 2)];   // L1 hit: touched in fwd sweep
        float2 o;
        // lane 0
        {
            float xl = LX[tt].x, tl = LT[tt].x, tv = tv2.x;
            float den = nt0 - tl;
            float r = xl + (nx0 - xl) * __fdividef(tv - tl, den);
            bool ok = (den != 0.f) && isfinite(r);
            if ((bA >> tt) & 1u) {
                o.x = xl;                        // observed: forward fill == v
                nx0 = xl; nt0 = tv;
            } else {
                o.x = ok ? r : 0.f;
            }
        }
        // lane 1
        {
            float xl = LX[tt].y, tl = LT[tt].y, tv = tv2.y;
            float den = nt1 - tl;
            float r = xl + (nx1 - xl) * __fdividef(tv - tl, den);
            bool ok = (den != 0.f) && isfinite(r);
            if ((bB >> tt) & 1u) {
                o.y = xl;
                nx1 = xl; nt1 = tv;
            } else {
                o.y = ok ? r : 0.f;
            }
        }
        o2[base2 + tt * (ND / 2)] = o;
    }
}

// ---------------------------------------------------------------------------
extern "C" void kernel_launch(void* const* d_in, const int* in_sizes, int n_in,
                              void* d_out, int out_size) {
    const float* values = (const float*)d_in[0];
    const float* times  = (const float*)d_in[1];
    const void*  mask   = d_in[2];

    (void)n_in; (void)in_sizes; (void)out_size;

    // Single fused launch: streams mask (+probe overage), v, t once;
    // writes out once.
    k_all<<<(NB * NC * (ND / 2)) / 128, 128>>>(values, times, mask, (float*)d_out);
}